// round 17
// baseline (speedup 1.0000x reference)
#include <cuda_runtime.h>
#include <float.h>
#include <stdint.h>

#define NMAX 4096
#define DIMK 256              // fp32 features per row
#define NSC  2                // 16KB sub-chunks per 128-row block (128 int8 kcols each)
#define NSTG 2                // smem pipeline stages (1 supertile per stage)
#define NTHR 512
#define SUB_BYTES   16384     // one 128x128 int8 sub-chunk, pre-swizzled
#define BLOCK_BYTES 32768     // full 128x256 int8 block (2 contiguous sub-chunks)

// ---------------- device scratch (no allocs allowed) ----------------
__device__ int    g_posmax[NMAX];                // max d^2 over positives, float bits
__device__ int    g_negmin[NMAX];                // min d^2 over negatives, float bits
__device__ float  g_xx[NMAX];                    // squared norms (exact fp32)
__device__ float  g_sc[NMAX];                    // per-row quant scale
__device__ int    g_lab[NMAX];                   // normalized labels
__device__ int    g_done;
// chunk-major pre-swizzled int8 features:
// block b = row/128, sub-chunk c = col/128 -> contiguous 16KB at ((b*2+c)<<14)
__device__ __align__(16) int8_t g_i8s[NMAX * DIMK];

// ---------------- PTX helpers (sm_90-baseline ISA) ----------------
__device__ __forceinline__ uint32_t s2u(const void* p) {
    uint32_t a;
    asm("{ .reg .u64 t; cvta.to.shared.u64 t, %1; cvt.u32.u64 %0, t; }" : "=r"(a) : "l"(p));
    return a;
}
#define MBAR_INIT(a, c) asm volatile("mbarrier.init.shared.b64 [%0], %1;" :: "r"(a), "r"(c) : "memory")
#define MBAR_EXPECT_TX(a, b) asm volatile("mbarrier.arrive.expect_tx.shared.b64 _, [%0], %1;" :: "r"(a), "r"(b) : "memory")
#define MBAR_ARRIVE(a) asm volatile("mbarrier.arrive.release.cta.shared.b64 _, [%0];" :: "r"(a) : "memory")
#define FENCE_ASYNC()  asm volatile("fence.proxy.async.shared::cta;" ::: "memory")
__device__ __forceinline__ void mbar_wait(uint32_t mbar, uint32_t parity) {
    asm volatile(
        "{\n\t.reg .pred P;\n\t"
        "WL_%=:\n\t"
        "mbarrier.try_wait.parity.acquire.cta.shared::cta.b64 P, [%0], %1, 0x989680;\n\t"
        "@!P bra WL_%=;\n\t}"
        :: "r"(mbar), "r"(parity) : "memory");
}
__device__ __forceinline__ void bulk_g2s(uint32_t dst, const void* src, uint32_t mbar) {
    asm volatile(
        "cp.async.bulk.shared::cluster.global.mbarrier::complete_tx::bytes "
        "[%0], [%1], %2, [%3];"
        :: "r"(dst), "l"(src), "r"((uint32_t)BLOCK_BYTES), "r"(mbar) : "memory");
}
__device__ __forceinline__ void ldsm4(uint32_t* r, uint32_t a) {
    asm volatile("ldmatrix.sync.aligned.m8n8.x4.shared.b16 {%0,%1,%2,%3}, [%4];"
                 : "=r"(r[0]), "=r"(r[1]), "=r"(r[2]), "=r"(r[3]) : "r"(a));
}
// int8 k32 MMA: byte-layout identical to f16 k16 (16 rows x 32B fragments)
__device__ __forceinline__ void mma_s8(int* d, const uint32_t* a,
                                       uint32_t b0, uint32_t b1) {
    asm volatile(
        "mma.sync.aligned.m16n8k32.row.col.s32.s8.s8.s32 "
        "{%0,%1,%2,%3}, {%4,%5,%6,%7}, {%8,%9}, {%0,%1,%2,%3};"
        : "+r"(d[0]), "+r"(d[1]), "+r"(d[2]), "+r"(d[3])
        : "r"(a[0]), "r"(a[1]), "r"(a[2]), "r"(a[3]), "r"(b0), "r"(b1));
}
__device__ __forceinline__ int ldcg_i(const int* p) {
    int v; asm volatile("ld.global.cg.s32 %0, [%1];" : "=r"(v) : "l"(p)); return v;
}
#define SWZ(x) ((x) ^ ((((uint32_t)(x)) >> 3) & 0x70))

// SMEM layout (relative to 1024-aligned base)
#define SM_FULL   0           // 2 x 8B mbarriers
#define SM_EMPTY  64          // 2 x 8B mbarriers
#define SM_FLAG   128
// epilogue-operand double buffer: 2 sets x 4608B
//  set layout: xxi[128]f @0, sci[128]f @512, labi[128]i @1024,
//              xxj[256]f @1536, scj[256]f @2560, labj[256]i @3584
#define SM_EPI    256
#define EPI_SET   4608
#define SM_STAGE  10240       // 2 stages x 96KB: A(32K) | B0(32K) | B1(32K)
#define STAGE_SZ  98304
#define SMEM_TOTAL (SM_STAGE + NSTG * STAGE_SZ + 1024)   // ~203KB -> 1 CTA/SM

// ---------------------------------------------------------------------------
// Prep: int8 quantize (per-row scale) into chunk-major PRE-SWIZZLED layout,
// exact fp32 norms, scales, labels, init. One warp per row.
// ---------------------------------------------------------------------------
__global__ void prep_kernel(const float* __restrict__ feat,
                            const int* __restrict__ lab_raw, int n) {
    int row  = blockIdx.x * 8 + (threadIdx.x >> 5);
    int lane = threadIdx.x & 31;
    if (row >= n) return;

    const float4* p = (const float4*)(feat + (size_t)row * DIMK);
    float4 v0 = p[2 * lane];          // cols lane*8 .. lane*8+3
    float4 v1 = p[2 * lane + 1];      // cols lane*8+4 .. lane*8+7

    float s = v0.x * v0.x + v0.y * v0.y + v0.z * v0.z + v0.w * v0.w
            + v1.x * v1.x + v1.y * v1.y + v1.z * v1.z + v1.w * v1.w;
    float m = fmaxf(fmaxf(fmaxf(fabsf(v0.x), fabsf(v0.y)), fmaxf(fabsf(v0.z), fabsf(v0.w))),
                    fmaxf(fmaxf(fabsf(v1.x), fabsf(v1.y)), fmaxf(fabsf(v1.z), fabsf(v1.w))));
#pragma unroll
    for (int o = 16; o; o >>= 1) {
        s += __shfl_xor_sync(0xffffffffu, s, o);
        m = fmaxf(m, __shfl_xor_sync(0xffffffffu, m, o));
    }
    const float inv = (m > 0.f) ? 127.f / m : 0.f;

    float vv[8] = {v0.x, v0.y, v0.z, v0.w, v1.x, v1.y, v1.z, v1.w};
    uint8_t qb[8];
#pragma unroll
    for (int k = 0; k < 8; k++) {
        int q = __float2int_rn(vv[k] * inv);
        q = max(-127, min(127, q));
        qb[k] = (uint8_t)(int8_t)q;
    }
    uint64_t pk;
    memcpy(&pk, qb, 8);

    const int blk = row >> 7;
    const int c   = lane >> 4;                 // sub-chunk = (lane*8)/128
    const uint32_t gr = SWZ(((uint32_t)(row & 127)) * 128 + (((lane & 15) >> 1) << 4))
                      + (uint32_t)(lane & 1) * 8;
    char* dst = (char*)g_i8s + (((size_t)blk * NSC + c) << 14) + gr;
    *(uint64_t*)dst = pk;

    if (lane == 0) {
        g_xx[row]     = s;
        g_sc[row]     = (m > 0.f) ? m / 127.f : 0.f;
        g_posmax[row] = 0;
        g_negmin[row] = __float_as_int(FLT_MAX);
    }
    if (lane == 1) {
        bool is64 = true;
#pragma unroll
        for (int i = 0; i < 32; i++)
            if (lab_raw[2 * i + 1] != 0) { is64 = false; break; }
        g_lab[row] = is64 ? lab_raw[2 * row] : lab_raw[row];
    }
    if (row == 0 && lane == 2) g_done = 0;
}

// ---------------------------------------------------------------------------
// Supertile enumeration: (ti, sj), sj covers j-blocks {2sj, 2sj+1}.
// Count = 272 for ntb=32. Duplicate transpose halves harmless (idempotent).
// ---------------------------------------------------------------------------
__device__ __forceinline__ void decode_st(int t, int nsb, int& ti, int& sj) {
    ti = 0;
    while (t >= nsb - (ti >> 1)) { t -= nsb - (ti >> 1); ti++; }
    sj = (ti >> 1) + t;
}

// Issue a whole supertile's operands (K=256): A + B0 + B1, three 32KB copies.
__device__ __forceinline__ void issue_supertile(uint32_t st, uint32_t fb,
                                                int ti, int sj) {
    MBAR_EXPECT_TX(fb, 3 * BLOCK_BYTES);
    const char* A  = (const char*)g_i8s + (((size_t)ti)           * NSC << 14);
    const char* B0 = (const char*)g_i8s + (((size_t)(2 * sj))     * NSC << 14);
    const char* B1 = (const char*)g_i8s + (((size_t)(2 * sj + 1)) * NSC << 14);
    bulk_g2s(st,                   A,  fb);
    bulk_g2s(st + BLOCK_BYTES,     B0, fb);
    bulk_g2s(st + 2 * BLOCK_BYTES, B1, fb);
}

// Full K=256 MMA for one supertile, per-warp 32x64 output (s32 acc).
__device__ __forceinline__ void mma_supertile(int acc[2][8][4], uint32_t st,
                                              int m_base, int n_base, int lane) {
    const uint32_t sA = st;
    const uint32_t sB = st + BLOCK_BYTES + ((uint32_t)(n_base >> 7)) * BLOCK_BYTES;
    const int nloc = n_base & 127;               // 0 or 64 within B block
#pragma unroll
    for (int ks = 0; ks < 8; ks++) {              // k32 steps over K=256
        const uint32_t so   = (uint32_t)(ks >> 2) * SUB_BYTES;
        const uint32_t koff = (uint32_t)(ks & 3) * 32 + ((lane >> 4) << 4);
        uint32_t a[2][4], b[4][4];
#pragma unroll
        for (int mt = 0; mt < 2; mt++) {
            uint32_t ad = SWZ((uint32_t)(m_base + mt * 16 + (lane & 15)) * 128 + koff);
            ldsm4(a[mt], sA + so + ad);
        }
#pragma unroll
        for (int p = 0; p < 4; p++) {
            uint32_t bd = SWZ((uint32_t)(nloc + p * 16 + (lane & 15)) * 128 + koff);
            ldsm4(b[p], sB + so + bd);
        }
#pragma unroll
        for (int mt = 0; mt < 2; mt++)
#pragma unroll
            for (int nt = 0; nt < 8; nt++) {
                const int p = nt >> 1, q = nt & 1;
                mma_s8(acc[mt][nt], a[mt], b[p][q], b[p][2 + q]);
            }
    }
}

// Stage one tile's epilogue operands into smem set `set` (no sync inside).
__device__ __forceinline__ void stage_epi(char* sm, int set, int ti, int sj, int tid) {
    char* base = sm + SM_EPI + set * EPI_SET;
    if (tid < 128) {
        ((float*)(base +    0))[tid] = g_xx[ti * 128 + tid];
        ((float*)(base +  512))[tid] = g_sc[ti * 128 + tid];
        ((int*)  (base + 1024))[tid] = g_lab[ti * 128 + tid];
    } else if (tid < 384) {
        int q = tid - 128;
        ((float*)(base + 1536))[q] = g_xx[sj * 256 + q];
        ((float*)(base + 2560))[q] = g_sc[sj * 256 + q];
        ((int*)  (base + 3584))[q] = g_lab[sj * 256 + q];
    }
}

// ---------------------------------------------------------------------------
// Persistent kernel: G<=2 supertiles per CTA -> pre-staged epilogue operands,
// ZERO mid-loop __syncthreads, no empty-barrier traffic; per-warp epilogue
// overlaps other warps' MMA. Fused final reduction.
// ---------------------------------------------------------------------------
__global__ void __launch_bounds__(NTHR, 1) tile_kernel(float* __restrict__ out, int n) {
    extern __shared__ char smem_raw[];
    uint32_t sb_raw = s2u(smem_raw);
    uint32_t pad = (1024u - (sb_raw & 1023u)) & 1023u;
    char* sm = smem_raw + pad;
    uint32_t sb = sb_raw + pad;

    const int tid = threadIdx.x, lane = tid & 31, w = tid >> 5;
    const int m_base = (w & 3) * 32;     // 4 warps along M (128 rows)
    const int n_base = (w >> 2) * 64;    // 4 warps along N (256 cols)

    const int ntb = n >> 7;
    const int nsb = ntb >> 1;
    int ST = 0;
    for (int t2 = 0; t2 < ntb; t2++) ST += nsb - (t2 >> 1);
    const int G = (ST - (int)blockIdx.x + (int)gridDim.x - 1) / (int)gridDim.x;

    if (tid == 0) {
#pragma unroll
        for (int s = 0; s < NSTG; s++) {
            MBAR_INIT(sb + SM_FULL + s * 8, 1);
            MBAR_INIT(sb + SM_EMPTY + s * 8, 16);
        }
    }
    __syncthreads();

    if (G > 0) {
        // prologue: issue TMA for (up to) both supertiles, pre-stage BOTH
        // tiles' epilogue operands.
#pragma unroll
        for (int gg = 0; gg < NSTG; gg++) {
            if (gg < G) {
                int tg, sg;
                decode_st((int)blockIdx.x + gg * (int)gridDim.x, nsb, tg, sg);
                if (tid == 0)
                    issue_supertile(sb + SM_STAGE + gg * STAGE_SZ,
                                    sb + SM_FULL + gg * 8, tg, sg);
                stage_epi(sm, gg, tg, sg, tid);
            }
        }
        __syncthreads();                          // operands staged for all g<2

        int acc[2][8][4];

        for (int g = 0; g < G; g++) {
            const int s = g & 1;
            int ti, sj;
            decode_st((int)blockIdx.x + g * (int)gridDim.x, nsb, ti, sj);

            if (g >= NSTG) {
                // generic path (never taken for n=4096): restage + refill
                __syncthreads();
                stage_epi(sm, s, ti, sj, tid);
                __syncthreads();
            }
            if (tid == 0 && g >= 1 && g + 1 < G) {
                mbar_wait(sb + SM_EMPTY + (s ^ 1) * 8, (uint32_t)(((g - 1) >> 1) & 1));
                FENCE_ASYNC();
                int lti, lsj;
                decode_st((int)blockIdx.x + (g + 1) * (int)gridDim.x, nsb, lti, lsj);
                issue_supertile(sb + SM_STAGE + (s ^ 1) * STAGE_SZ,
                                sb + SM_FULL + (s ^ 1) * 8, lti, lsj);
            }

#pragma unroll
            for (int a = 0; a < 2; a++)
#pragma unroll
                for (int b = 0; b < 8; b++)
#pragma unroll
                    for (int e = 0; e < 4; e++) acc[a][b][e] = 0;

            mbar_wait(sb + SM_FULL + s * 8, (uint32_t)((g >> 1) & 1));
            mma_supertile(acc, sb + SM_STAGE + s * STAGE_SZ, m_base, n_base, lane);
            if (G > NSTG && lane == 0) MBAR_ARRIVE(sb + SM_EMPTY + s * 8);

            // ---- per-warp epilogue (overlaps other warps' MMA) ----
            char* eb = sm + SM_EPI + s * EPI_SET;
            float* xxi_s  = (float*)(eb +    0);
            float* sci_s  = (float*)(eb +  512);
            int*   labi_s = (int*)  (eb + 1024);
            float* xxj_s  = (float*)(eb + 1536);
            float* scj_s  = (float*)(eb + 2560);
            int*   labj_s = (int*)  (eb + 3584);

            float xi[4], m2si[4]; int li[4];
#pragma unroll
            for (int mt = 0; mt < 2; mt++)
#pragma unroll
                for (int rh = 0; rh < 2; rh++) {
                    int r = m_base + mt * 16 + (lane >> 2) + 8 * rh;
                    xi[mt * 2 + rh]   = xxi_s[r];
                    li[mt * 2 + rh]   = labi_s[r];
                    m2si[mt * 2 + rh] = -2.f * sci_s[r];
                }
            float xj[16], sjv[16]; int lj[16];
#pragma unroll
            for (int nt = 0; nt < 8; nt++)
#pragma unroll
                for (int cc = 0; cc < 2; cc++) {
                    int q = n_base + nt * 8 + (lane & 3) * 2 + cc;
                    xj[nt * 2 + cc]  = xxj_s[q];
                    lj[nt * 2 + cc]  = labj_s[q];
                    sjv[nt * 2 + cc] = scj_s[q];
                }
            float d2v[2][8][4];
#pragma unroll
            for (int mt = 0; mt < 2; mt++)
#pragma unroll
                for (int nt = 0; nt < 8; nt++)
#pragma unroll
                    for (int e = 0; e < 4; e++) {
                        int rh = e >> 1, cc = e & 1;
                        d2v[mt][nt][e] = fmaf(m2si[mt * 2 + rh] * sjv[nt * 2 + cc],
                                              (float)acc[mt][nt][e],
                                              xi[mt * 2 + rh] + xj[nt * 2 + cc]);
                    }

            // row direction
#pragma unroll
            for (int mt = 0; mt < 2; mt++)
#pragma unroll
                for (int rh = 0; rh < 2; rh++) {
                    float pm = -1.f, nm = FLT_MAX;
                    const int L = li[mt * 2 + rh];
#pragma unroll
                    for (int nt = 0; nt < 8; nt++)
#pragma unroll
                        for (int cc = 0; cc < 2; cc++) {
                            float v = d2v[mt][nt][rh * 2 + cc];
                            if (L == lj[nt * 2 + cc]) pm = fmaxf(pm, v);
                            else                      nm = fminf(nm, v);
                        }
                    pm = fmaxf(pm, __shfl_xor_sync(0xffffffffu, pm, 1));
                    pm = fmaxf(pm, __shfl_xor_sync(0xffffffffu, pm, 2));
                    nm = fminf(nm, __shfl_xor_sync(0xffffffffu, nm, 1));
                    nm = fminf(nm, __shfl_xor_sync(0xffffffffu, nm, 2));
                    if ((lane & 3) == 0) {
                        int gi = ti * 128 + m_base + mt * 16 + (lane >> 2) + 8 * rh;
                        atomicMax(&g_posmax[gi], __float_as_int(pm));
                        atomicMin(&g_negmin[gi], __float_as_int(nm));
                    }
                }

            // column direction (symmetry)
#pragma unroll
            for (int nt = 0; nt < 8; nt++)
#pragma unroll
                for (int cc = 0; cc < 2; cc++) {
                    float pm = -1.f, nm = FLT_MAX;
                    const int L = lj[nt * 2 + cc];
#pragma unroll
                    for (int mt = 0; mt < 2; mt++)
#pragma unroll
                        for (int rh = 0; rh < 2; rh++) {
                            float v = d2v[mt][nt][rh * 2 + cc];
                            if (L == li[mt * 2 + rh]) pm = fmaxf(pm, v);
                            else                      nm = fminf(nm, v);
                        }
                    pm = fmaxf(pm, __shfl_xor_sync(0xffffffffu, pm, 4));
                    pm = fmaxf(pm, __shfl_xor_sync(0xffffffffu, pm, 8));
                    pm = fmaxf(pm, __shfl_xor_sync(0xffffffffu, pm, 16));
                    nm = fminf(nm, __shfl_xor_sync(0xffffffffu, nm, 4));
                    nm = fminf(nm, __shfl_xor_sync(0xffffffffu, nm, 8));
                    nm = fminf(nm, __shfl_xor_sync(0xffffffffu, nm, 16));
                    if (lane < 4) {
                        int gj = sj * 256 + n_base + nt * 8 + (lane & 3) * 2 + cc;
                        atomicMax(&g_posmax[gj], __float_as_int(pm));
                        atomicMin(&g_negmin[gj], __float_as_int(nm));
                    }
                }
        }
    }

    // ---- completion counter: last CTA performs the finalize reduction ----
    __syncthreads();
    if (tid == 0) {
        __threadfence();
        int prev = atomicAdd(&g_done, 1);
        *(volatile int*)(sm + SM_FLAG) = (prev == (int)gridDim.x - 1) ? 1 : 0;
    }
    __syncthreads();
    if (*(volatile int*)(sm + SM_FLAG)) {
        float* ss = (float*)(sm + SM_STAGE);
        float* sc = ss + NTHR;
        float sum = 0.f, cnt = 0.f;
        for (int i = tid; i < n; i += NTHR) {
            float ap2 = __int_as_float(ldcg_i(&g_posmax[i]));
            float ap  = sqrtf(fmaxf(ap2, 1e-12f));
            float nm2 = __int_as_float(ldcg_i(&g_negmin[i]));
            bool  has_neg = nm2 < 1e30f;
            float an  = has_neg ? sqrtf(fmaxf(nm2, 1e-12f)) : 0.f;
            bool  valid = (ap < 1000000.0f) && (an > 0.f);
            if (valid) {
                sum += fmaxf(0.3f + ap - an, 0.f);
                cnt += 1.f;
            }
        }
        ss[tid] = sum;
        sc[tid] = cnt;
        __syncthreads();
        for (int o = NTHR / 2; o; o >>= 1) {
            if (tid < o) {
                ss[tid] += ss[tid + o];
                sc[tid] += sc[tid + o];
            }
            __syncthreads();
        }
        if (tid == 0)
            out[0] = (sc[0] > 0.f) ? ss[0] / fmaxf(sc[0], 1.f) : 0.f;
    }
}

// ---------------------------------------------------------------------------
extern "C" void kernel_launch(void* const* d_in, const int* in_sizes, int n_in,
                              void* d_out, int out_size) {
    const float* feat   = (const float*)d_in[0];
    const int*   labels = (const int*)d_in[1];   // int32/int64 auto-detected
    int n = in_sizes[1];                         // 4096

    cudaFuncSetAttribute(tile_kernel, cudaFuncAttributeMaxDynamicSharedMemorySize,
                         SMEM_TOTAL);

    prep_kernel<<<(n + 7) / 8, 256>>>(feat, labels, n);
    tile_kernel<<<148, NTHR, SMEM_TOTAL>>>((float*)d_out, n);
}